// round 2
// baseline (speedup 1.0000x reference)
#include <cuda_runtime.h>
#include <math.h>

// ScaledDotProduct: out = softmax(Q K^T / sqrt(D)) V
// Shapes fixed by the problem: B=4, H=16, S=2048, D=64, fp32.
//
// Round-1: resubmission of the fp32 CUDA-core flash-attention baseline
// (rounds 0-1 failed on container acquisition, not kernel content).
// Compute-bound on the FFMA pipe by design; tcgen05 tensor-core port is
// the planned follow-up once a baseline pass + rel_err slack is measured.

namespace {
constexpr int BH       = 64;    // B*H
constexpr int SEQ      = 2048;
constexpr int DH       = 64;
constexpr int BR       = 64;    // Q rows per CTA
constexpr int BC       = 64;    // KV rows per tile
constexpr int SPAD     = 68;    // smem row stride in floats (bank-conflict-free)
constexpr int NTHREADS = 128;
constexpr int NTILES   = SEQ / BC;
constexpr size_t SMEM_BYTES = (size_t)(BR + BC + BC + BR) * SPAD * sizeof(float); // 69632
}

__global__ __launch_bounds__(NTHREADS, 3)
void fa_fp32_kernel(const float* __restrict__ Q, const float* __restrict__ K,
                    const float* __restrict__ V, float* __restrict__ Out) {
    extern __shared__ float smem[];
    float* Qs = smem;                 // [BR][SPAD]
    float* Ks = Qs + BR * SPAD;       // [BC][SPAD]
    float* Vs = Ks + BC * SPAD;       // [BC][SPAD]
    float* Ps = Vs + BC * SPAD;       // [BR][SPAD]

    const int tid = threadIdx.x;
    const int tx  = tid & 7;          // 0..7  -> col group
    const int ty  = tid >> 3;         // 0..15 -> row group
    const int bh  = blockIdx.y;
    const int q0  = blockIdx.x * BR;

    const float* Qg = Q + ((size_t)bh * SEQ + q0) * DH;
    const float* Kg = K + (size_t)bh * SEQ * DH;
    const float* Vg = V + (size_t)bh * SEQ * DH;
    float*       Og = Out + ((size_t)bh * SEQ + q0) * DH;

    // ---- Load Q tile, fold in 1/sqrt(D) ----
    #pragma unroll
    for (int it = 0; it < (BR * DH / 4) / NTHREADS; ++it) {
        int idx = tid + it * NTHREADS;
        int r   = idx >> 4;
        int c   = (idx & 15) << 2;
        float4 v = *reinterpret_cast<const float4*>(&Qg[r * DH + c]);
        v.x *= 0.125f; v.y *= 0.125f; v.z *= 0.125f; v.w *= 0.125f;
        *reinterpret_cast<float4*>(&Qs[r * SPAD + c]) = v;
    }

    float accO[4][8];
    #pragma unroll
    for (int i = 0; i < 4; ++i)
        #pragma unroll
        for (int j = 0; j < 8; ++j) accO[i][j] = 0.f;
    float m_i[4] = {-INFINITY, -INFINITY, -INFINITY, -INFINITY};
    float l_i[4] = {0.f, 0.f, 0.f, 0.f};

    for (int kt = 0; kt < NTILES; ++kt) {
        __syncthreads();   // previous iteration's reads of Ks/Vs/Ps complete

        // ---- Load K,V tile ----
        const float* Kt = Kg + (size_t)kt * BC * DH;
        const float* Vt = Vg + (size_t)kt * BC * DH;
        #pragma unroll
        for (int it = 0; it < (BC * DH / 4) / NTHREADS; ++it) {
            int idx = tid + it * NTHREADS;
            int r   = idx >> 4;
            int c   = (idx & 15) << 2;
            *reinterpret_cast<float4*>(&Ks[r * SPAD + c]) =
                *reinterpret_cast<const float4*>(&Kt[r * DH + c]);
            *reinterpret_cast<float4*>(&Vs[r * SPAD + c]) =
                *reinterpret_cast<const float4*>(&Vt[r * DH + c]);
        }
        __syncthreads();

        // ---- S = Qs * Ks^T  (per-thread 4x8 tile: rows ty+16i, cols tx+8j) ----
        float acc[4][8];
        #pragma unroll
        for (int i = 0; i < 4; ++i)
            #pragma unroll
            for (int j = 0; j < 8; ++j) acc[i][j] = 0.f;

        #pragma unroll
        for (int d = 0; d < DH; d += 4) {
            float4 q4[4];
            #pragma unroll
            for (int i = 0; i < 4; ++i)
                q4[i] = *reinterpret_cast<const float4*>(&Qs[(ty + 16 * i) * SPAD + d]);
            #pragma unroll
            for (int jh = 0; jh < 2; ++jh) {
                float4 k4[4];
                #pragma unroll
                for (int jj = 0; jj < 4; ++jj)
                    k4[jj] = *reinterpret_cast<const float4*>(
                        &Ks[(tx + 8 * (jh * 4 + jj)) * SPAD + d]);
                #pragma unroll
                for (int i = 0; i < 4; ++i)
                    #pragma unroll
                    for (int jj = 0; jj < 4; ++jj) {
                        int j = jh * 4 + jj;
                        acc[i][j] += q4[i].x * k4[jj].x;
                        acc[i][j] += q4[i].y * k4[jj].y;
                        acc[i][j] += q4[i].z * k4[jj].z;
                        acc[i][j] += q4[i].w * k4[jj].w;
                    }
            }
        }

        // ---- Online softmax (row stats shared by the 8 lanes of one ty group) ----
        #pragma unroll
        for (int i = 0; i < 4; ++i) {
            float mx = acc[i][0];
            #pragma unroll
            for (int j = 1; j < 8; ++j) mx = fmaxf(mx, acc[i][j]);
            #pragma unroll
            for (int off = 4; off >= 1; off >>= 1)
                mx = fmaxf(mx, __shfl_xor_sync(0xffffffffu, mx, off));

            float m_new = fmaxf(m_i[i], mx);
            float corr  = __expf(m_i[i] - m_new);   // expf(-inf)=0 on first tile
            m_i[i] = m_new;

            float rsum = 0.f;
            #pragma unroll
            for (int j = 0; j < 8; ++j) {
                float p = __expf(acc[i][j] - m_new);
                acc[i][j] = p;
                rsum += p;
            }
            #pragma unroll
            for (int off = 4; off >= 1; off >>= 1)
                rsum += __shfl_xor_sync(0xffffffffu, rsum, off);

            l_i[i] = l_i[i] * corr + rsum;
            #pragma unroll
            for (int j = 0; j < 8; ++j) accO[i][j] *= corr;

            #pragma unroll
            for (int j = 0; j < 8; ++j)
                Ps[(ty + 16 * i) * SPAD + tx + 8 * j] = acc[i][j];
        }
        __syncthreads();   // Ps complete before PV reads

        // ---- O += P * V  (rows ty+16i, d-cols tx+8j) ----
        #pragma unroll
        for (int c = 0; c < BC; c += 4) {
            float4 p4[4];
            #pragma unroll
            for (int i = 0; i < 4; ++i)
                p4[i] = *reinterpret_cast<const float4*>(&Ps[(ty + 16 * i) * SPAD + c]);
            #pragma unroll
            for (int cc = 0; cc < 4; ++cc) {
                float vv[8];
                #pragma unroll
                for (int j = 0; j < 8; ++j)
                    vv[j] = Vs[(c + cc) * SPAD + tx + 8 * j];
                #pragma unroll
                for (int i = 0; i < 4; ++i) {
                    float p = reinterpret_cast<const float*>(&p4[i])[cc];
                    #pragma unroll
                    for (int j = 0; j < 8; ++j)
                        accO[i][j] += p * vv[j];
                }
            }
        }
    }

    // ---- Normalize and store ----
    #pragma unroll
    for (int i = 0; i < 4; ++i) {
        float inv = __fdividef(1.0f, l_i[i]);
        #pragma unroll
        for (int j = 0; j < 8; ++j)
            Og[(ty + 16 * i) * DH + tx + 8 * j] = accO[i][j] * inv;
    }
}

extern "C" void kernel_launch(void* const* d_in, const int* in_sizes, int n_in,
                              void* d_out, int out_size) {
    const float* q = (const float*)d_in[0];
    const float* k = (const float*)d_in[1];
    const float* v = (const float*)d_in[2];
    float*       o = (float*)d_out;
    (void)in_sizes; (void)n_in; (void)out_size;

    // cudaFuncSetAttribute is not stream-ordered: safe under graph capture,
    // idempotent, no allocation.
    cudaFuncSetAttribute(fa_fp32_kernel,
                         cudaFuncAttributeMaxDynamicSharedMemorySize,
                         (int)SMEM_BYTES);

    dim3 grid(SEQ / BR, BH);   // 32 x 64 = 2048 CTAs
    fa_fp32_kernel<<<grid, NTHREADS, SMEM_BYTES>>>(q, k, v, o);
}

// round 4
// speedup vs baseline: 3.1401x; 3.1401x over previous
#include <cuda_runtime.h>
#include <cuda_bf16.h>
#include <cstdint>
#include <math.h>

// ScaledDotProduct: out = softmax(Q K^T / sqrt(D)) V
// B=4, H=16, S=2048, D=64, fp32 in/out.
//
// bf16 split-precision tensor-core flash attention.
// Each fp32 operand x is split as x = hi + lo (hi = truncate-to-bf16(x),
// lo = bf16(x - hi)); products use 3 MMAs (hi*hi + hi*lo + lo*hi), giving
// ~2^-17 relative error — far inside the 1e-3 budget (fp32 baseline
// rel_err was 1.15e-6, threshold slack 870x).
// Fixes vs round 3: <cstdint> include; V tile now genuinely transposed
// ([d][kv]) so the PV MMA multiplies P·V, not P·V^T.

namespace {
constexpr int BH       = 64;
constexpr int SEQ      = 2048;
constexpr int DH       = 64;
constexpr int BR       = 64;     // Q rows per CTA (4 warps x 16)
constexpr int BC       = 64;     // KV rows per tile
constexpr int NTHREADS = 128;
constexpr int NTILES   = SEQ / BC;
constexpr int KST      = 72;     // smem row stride in bf16 halves
constexpr int TILE_H   = 64 * KST;
constexpr size_t SMEM_BYTES = 6ull * TILE_H * sizeof(unsigned short); // 55296 B
}

// pack hi (truncated) bf16x2 of (x0,x1) and bf16x2 of the residuals
__device__ __forceinline__ void split2(float x0, float x1, uint32_t& hi2, uint32_t& lo2) {
    uint32_t u0 = __float_as_uint(x0), u1 = __float_as_uint(x1);
    uint32_t h0 = u0 & 0xFFFF0000u,   h1 = u1 & 0xFFFF0000u;
    hi2 = (u0 >> 16) | h1;                       // low half = x0_hi, high = x1_hi
    float l0 = x0 - __uint_as_float(h0);
    float l1 = x1 - __uint_as_float(h1);
    // cvt.rn.bf16x2.f32 d, a, b  ->  d.hi = bf16(a), d.lo = bf16(b)
    asm("cvt.rn.bf16x2.f32 %0, %1, %2;" : "=r"(lo2) : "f"(l1), "f"(l0));
}

__device__ __forceinline__ void mma_bf16(float* c, const uint32_t* a, uint32_t b0, uint32_t b1) {
    asm volatile(
        "mma.sync.aligned.m16n8k16.row.col.f32.bf16.bf16.f32 "
        "{%0,%1,%2,%3}, {%4,%5,%6,%7}, {%8,%9}, {%0,%1,%2,%3};\n"
        : "+f"(c[0]), "+f"(c[1]), "+f"(c[2]), "+f"(c[3])
        : "r"(a[0]), "r"(a[1]), "r"(a[2]), "r"(a[3]), "r"(b0), "r"(b1));
}

__global__ __launch_bounds__(NTHREADS, 2)
void fa_bf16split_kernel(const float* __restrict__ Q, const float* __restrict__ K,
                         const float* __restrict__ V, float* __restrict__ Out) {
    extern __shared__ __align__(16) unsigned short sm[];
    unsigned short* Qhi = sm;                 // [qr][d]
    unsigned short* Qlo = Qhi + TILE_H;
    unsigned short* Khi = Qlo + TILE_H;       // [kv][d]
    unsigned short* Klo = Khi + TILE_H;
    unsigned short* Vhi = Klo + TILE_H;       // [d][kv]  (transposed!)
    unsigned short* Vlo = Vhi + TILE_H;

    const int tid = threadIdx.x;
    const int wid = tid >> 5;
    const int lid = tid & 31;
    const int g   = lid >> 2;     // 0..7 fragment row group
    const int t   = lid & 3;      // 0..3 thread-in-group
    const int bh  = blockIdx.y;
    const int q0  = blockIdx.x * BR;

    const float* Qg = Q + ((size_t)bh * SEQ + q0) * DH;
    const float* Kg = K + (size_t)bh * SEQ * DH;
    const float* Vg = V + (size_t)bh * SEQ * DH;
    float*       Og = Out + ((size_t)bh * SEQ + q0) * DH;

    // ---- Load + split Q (scale 1/8 folded in) ----
    #pragma unroll
    for (int it = 0; it < 8; ++it) {
        int idx = tid + it * NTHREADS;       // float4 index
        int r   = idx >> 4;
        int c   = (idx & 15) << 2;
        float4 v = *reinterpret_cast<const float4*>(&Qg[r * DH + c]);
        v.x *= 0.125f; v.y *= 0.125f; v.z *= 0.125f; v.w *= 0.125f;
        uint2 hi, lo;
        split2(v.x, v.y, hi.x, lo.x);
        split2(v.z, v.w, hi.y, lo.y);
        *reinterpret_cast<uint2*>(&Qhi[r * KST + c]) = hi;
        *reinterpret_cast<uint2*>(&Qlo[r * KST + c]) = lo;
    }
    __syncthreads();

    // ---- Persistent Q A-fragments (4 k-chunks, hi+lo, 4 regs each) ----
    uint32_t qfh[4][4], qfl[4][4];
    {
        const int qr = wid * 16 + g;
        #pragma unroll
        for (int kc = 0; kc < 4; ++kc) {
            int base = qr * KST + kc * 16 + 2 * t;
            qfh[kc][0] = *reinterpret_cast<const uint32_t*>(&Qhi[base]);
            qfh[kc][1] = *reinterpret_cast<const uint32_t*>(&Qhi[base + 8 * KST]);
            qfh[kc][2] = *reinterpret_cast<const uint32_t*>(&Qhi[base + 8]);
            qfh[kc][3] = *reinterpret_cast<const uint32_t*>(&Qhi[base + 8 * KST + 8]);
            qfl[kc][0] = *reinterpret_cast<const uint32_t*>(&Qlo[base]);
            qfl[kc][1] = *reinterpret_cast<const uint32_t*>(&Qlo[base + 8 * KST]);
            qfl[kc][2] = *reinterpret_cast<const uint32_t*>(&Qlo[base + 8]);
            qfl[kc][3] = *reinterpret_cast<const uint32_t*>(&Qlo[base + 8 * KST + 8]);
        }
    }

    float accO[8][4];
    #pragma unroll
    for (int nb = 0; nb < 8; ++nb)
        #pragma unroll
        for (int j = 0; j < 4; ++j) accO[nb][j] = 0.f;
    float m0 = -INFINITY, m1 = -INFINITY;
    float l0 = 0.f, l1 = 0.f;

    for (int kt = 0; kt < NTILES; ++kt) {
        __syncthreads();   // prior tile's smem reads complete

        // ---- K tile: row-major [kv][d], split to bf16 hi/lo ----
        const float* Kt = Kg + (size_t)kt * BC * DH;
        #pragma unroll
        for (int it = 0; it < 8; ++it) {
            int idx = tid + it * NTHREADS;
            int r   = idx >> 4;
            int c   = (idx & 15) << 2;
            float4 v = *reinterpret_cast<const float4*>(&Kt[r * DH + c]);
            uint2 hi, lo;
            split2(v.x, v.y, hi.x, lo.x);
            split2(v.z, v.w, hi.y, lo.y);
            *reinterpret_cast<uint2*>(&Khi[r * KST + c]) = hi;
            *reinterpret_cast<uint2*>(&Klo[r * KST + c]) = lo;
        }

        // ---- V tile: read V[kv][d] coalesced, store TRANSPOSED Vt[d][kv] ----
        const float* Vt = Vg + (size_t)kt * BC * DH;
        {
            int c  = tid & 63;                 // d column this thread reads
            int rg = (tid >> 6) * 4;           // kv row-group offset
            #pragma unroll
            for (int it = 0; it < 8; ++it) {
                int r = rg + it * 8;           // kv rows r..r+3
                float x0 = Vt[(r + 0) * DH + c];
                float x1 = Vt[(r + 1) * DH + c];
                float x2 = Vt[(r + 2) * DH + c];
                float x3 = Vt[(r + 3) * DH + c];
                uint32_t u0 = __float_as_uint(x0), u1 = __float_as_uint(x1);
                uint32_t u2 = __float_as_uint(x2), u3 = __float_as_uint(x3);
                uint32_t h0 = u0 & 0xFFFF0000u, h1 = u1 & 0xFFFF0000u;
                uint32_t h2 = u2 & 0xFFFF0000u, h3 = u3 & 0xFFFF0000u;
                float e0 = x0 - __uint_as_float(h0);
                float e1 = x1 - __uint_as_float(h1);
                float e2 = x2 - __uint_as_float(h2);
                float e3 = x3 - __uint_as_float(h3);
                // transposed store: element (d=c, kv=r+i) -> Vhi[c*KST + (r+i)]
                Vhi[c * KST + r + 0] = (unsigned short)(u0 >> 16);
                Vhi[c * KST + r + 1] = (unsigned short)(u1 >> 16);
                Vhi[c * KST + r + 2] = (unsigned short)(u2 >> 16);
                Vhi[c * KST + r + 3] = (unsigned short)(u3 >> 16);
                Vlo[c * KST + r + 0] = __bfloat16_as_ushort(__float2bfloat16(e0));
                Vlo[c * KST + r + 1] = __bfloat16_as_ushort(__float2bfloat16(e1));
                Vlo[c * KST + r + 2] = __bfloat16_as_ushort(__float2bfloat16(e2));
                Vlo[c * KST + r + 3] = __bfloat16_as_ushort(__float2bfloat16(e3));
            }
        }
        __syncthreads();

        // ---- S = Q K^T via 3-MMA bf16 split ----
        float accS[8][4];
        #pragma unroll
        for (int nb = 0; nb < 8; ++nb)
            #pragma unroll
            for (int j = 0; j < 4; ++j) accS[nb][j] = 0.f;

        #pragma unroll
        for (int kc = 0; kc < 4; ++kc) {
            #pragma unroll
            for (int nb = 0; nb < 8; ++nb) {
                int base = (nb * 8 + g) * KST + kc * 16 + 2 * t;
                uint32_t bh0 = *reinterpret_cast<const uint32_t*>(&Khi[base]);
                uint32_t bh1 = *reinterpret_cast<const uint32_t*>(&Khi[base + 8]);
                uint32_t bl0 = *reinterpret_cast<const uint32_t*>(&Klo[base]);
                uint32_t bl1 = *reinterpret_cast<const uint32_t*>(&Klo[base + 8]);
                mma_bf16(accS[nb], qfh[kc], bh0, bh1);
                mma_bf16(accS[nb], qfh[kc], bl0, bl1);
                mma_bf16(accS[nb], qfl[kc], bh0, bh1);
            }
        }

        // ---- Online softmax (rows g and g+8; quad = lanes sharing g) ----
        float mx0 = accS[0][0], mx1 = accS[0][2];
        #pragma unroll
        for (int nb = 0; nb < 8; ++nb) {
            mx0 = fmaxf(mx0, fmaxf(accS[nb][0], accS[nb][1]));
            mx1 = fmaxf(mx1, fmaxf(accS[nb][2], accS[nb][3]));
        }
        mx0 = fmaxf(mx0, __shfl_xor_sync(0xffffffffu, mx0, 1));
        mx0 = fmaxf(mx0, __shfl_xor_sync(0xffffffffu, mx0, 2));
        mx1 = fmaxf(mx1, __shfl_xor_sync(0xffffffffu, mx1, 1));
        mx1 = fmaxf(mx1, __shfl_xor_sync(0xffffffffu, mx1, 2));

        float mn0 = fmaxf(m0, mx0), mn1 = fmaxf(m1, mx1);
        float c0 = __expf(m0 - mn0), c1 = __expf(m1 - mn1);
        m0 = mn0; m1 = mn1;

        float rs0 = 0.f, rs1 = 0.f;
        #pragma unroll
        for (int nb = 0; nb < 8; ++nb) {
            accS[nb][0] = __expf(accS[nb][0] - mn0);
            accS[nb][1] = __expf(accS[nb][1] - mn0);
            accS[nb][2] = __expf(accS[nb][2] - mn1);
            accS[nb][3] = __expf(accS[nb][3] - mn1);
            rs0 += accS[nb][0] + accS[nb][1];
            rs1 += accS[nb][2] + accS[nb][3];
        }
        rs0 += __shfl_xor_sync(0xffffffffu, rs0, 1);
        rs0 += __shfl_xor_sync(0xffffffffu, rs0, 2);
        rs1 += __shfl_xor_sync(0xffffffffu, rs1, 1);
        rs1 += __shfl_xor_sync(0xffffffffu, rs1, 2);
        l0 = l0 * c0 + rs0;
        l1 = l1 * c1 + rs1;

        #pragma unroll
        for (int nb = 0; nb < 8; ++nb) {
            accO[nb][0] *= c0; accO[nb][1] *= c0;
            accO[nb][2] *= c1; accO[nb][3] *= c1;
        }

        // ---- Repack P (S accumulator) into A fragments, hi/lo split ----
        // A-frag for k-chunk kc: a0=(g, 16kc+2t) a1=(g+8, 16kc+2t)
        //                        a2=(g, 16kc+8+2t) a3=(g+8, 16kc+8+2t)
        uint32_t pfh[4][4], pfl[4][4];
        #pragma unroll
        for (int kc = 0; kc < 4; ++kc) {
            split2(accS[2 * kc][0],     accS[2 * kc][1],     pfh[kc][0], pfl[kc][0]);
            split2(accS[2 * kc][2],     accS[2 * kc][3],     pfh[kc][1], pfl[kc][1]);
            split2(accS[2 * kc + 1][0], accS[2 * kc + 1][1], pfh[kc][2], pfl[kc][2]);
            split2(accS[2 * kc + 1][2], accS[2 * kc + 1][3], pfh[kc][3], pfl[kc][3]);
        }

        // ---- O += P V via 3-MMA bf16 split (B frags from transposed V) ----
        #pragma unroll
        for (int kc = 0; kc < 4; ++kc) {
            #pragma unroll
            for (int nb = 0; nb < 8; ++nb) {
                int base = (nb * 8 + g) * KST + kc * 16 + 2 * t;
                uint32_t bh0 = *reinterpret_cast<const uint32_t*>(&Vhi[base]);
                uint32_t bh1 = *reinterpret_cast<const uint32_t*>(&Vhi[base + 8]);
                uint32_t bl0 = *reinterpret_cast<const uint32_t*>(&Vlo[base]);
                uint32_t bl1 = *reinterpret_cast<const uint32_t*>(&Vlo[base + 8]);
                mma_bf16(accO[nb], pfh[kc], bh0, bh1);
                mma_bf16(accO[nb], pfh[kc], bl0, bl1);
                mma_bf16(accO[nb], pfl[kc], bh0, bh1);
            }
        }
    }

    // ---- Normalize and store ----
    {
        float inv0 = __fdividef(1.0f, l0);
        float inv1 = __fdividef(1.0f, l1);
        int r0 = wid * 16 + g;
        #pragma unroll
        for (int nb = 0; nb < 8; ++nb) {
            int cc = nb * 8 + 2 * t;
            float2 o0 = make_float2(accO[nb][0] * inv0, accO[nb][1] * inv0);
            float2 o1 = make_float2(accO[nb][2] * inv1, accO[nb][3] * inv1);
            *reinterpret_cast<float2*>(&Og[r0 * DH + cc])       = o0;
            *reinterpret_cast<float2*>(&Og[(r0 + 8) * DH + cc]) = o1;
        }
    }
}

extern "C" void kernel_launch(void* const* d_in, const int* in_sizes, int n_in,
                              void* d_out, int out_size) {
    const float* q = (const float*)d_in[0];
    const float* k = (const float*)d_in[1];
    const float* v = (const float*)d_in[2];
    float*       o = (float*)d_out;
    (void)in_sizes; (void)n_in; (void)out_size;

    cudaFuncSetAttribute(fa_bf16split_kernel,
                         cudaFuncAttributeMaxDynamicSharedMemorySize,
                         (int)SMEM_BYTES);

    dim3 grid(SEQ / BR, BH);   // 32 x 64
    fa_bf16split_kernel<<<grid, NTHREADS, SMEM_BYTES>>>(q, k, v, o);
}